// round 7
// baseline (speedup 1.0000x reference)
#include <cuda_runtime.h>
#include <cuda_bf16.h>
#include <cstdint>

// Problem constants (fixed by reference setup_inputs)
#define BB 8
#define SS 2048
#define HH 1024
#define NTOK (BB * SS)                 // 16384
#define BSS ((long long)BB * SS * SS)  // 33,554,432
#define SSQ ((long long)SS * SS)       // 4,194,304 per batch

// Scratch: per-token combined scores. Non-candidates encoded as -1e30 so that
// pair_score = sS + sE + bm is guaranteed <= 0 -> invalid -> outputs 0.
__device__ float g_sS[NTOK];
__device__ float g_sE[NTOK];

// ---------------------------------------------------------------------------
// Phase 1 (per batch): token logits + scalar scores. One warp per token,
// 8 warps per block (measured-best R3 form). Weights in shared as SoA ->
// conflict-free LDS.128.
// ---------------------------------------------------------------------------
__global__ __launch_bounds__(256) void token_kernel(
    const float* __restrict__ rep,   // (B,S,H)
    const int*   __restrict__ mask,  // (B,S)
    const float* __restrict__ Ws,    // (H,2)
    const float* __restrict__ bs,    // (2,)
    const float* __restrict__ We,    // (H,2)
    const float* __restrict__ be,    // (2,)
    const float* __restrict__ Wm,    // (4,1)
    int tok_base)                    // first token of this batch chunk
{
    __shared__ float s_w0[HH];
    __shared__ float s_w1[HH];
    __shared__ float s_w2[HH];
    __shared__ float s_w3[HH];
    for (int h = threadIdx.x; h < HH; h += blockDim.x) {
        s_w0[h] = Ws[2 * h];
        s_w1[h] = Ws[2 * h + 1];
        s_w2[h] = We[2 * h];
        s_w3[h] = We[2 * h + 1];
    }
    __syncthreads();

    const int warp = threadIdx.x >> 5;
    const int lane = threadIdx.x & 31;
    const int t = tok_base + blockIdx.x * 8 + warp;

    const float4* __restrict__ r4 =
        reinterpret_cast<const float4*>(rep + (size_t)t * HH);

    float s0 = 0.f, s1 = 0.f, e0 = 0.f, e1 = 0.f;
#pragma unroll
    for (int it = 0; it < HH / 128; ++it) {
        const int idx = it * 32 + lane;
        const float4 r  = r4[idx];
        const float4 w0 = *reinterpret_cast<const float4*>(&s_w0[idx * 4]);
        const float4 w1 = *reinterpret_cast<const float4*>(&s_w1[idx * 4]);
        const float4 w2 = *reinterpret_cast<const float4*>(&s_w2[idx * 4]);
        const float4 w3 = *reinterpret_cast<const float4*>(&s_w3[idx * 4]);
        s0 += r.x * w0.x + r.y * w0.y + r.z * w0.z + r.w * w0.w;
        s1 += r.x * w1.x + r.y * w1.y + r.z * w1.z + r.w * w1.w;
        e0 += r.x * w2.x + r.y * w2.y + r.z * w2.z + r.w * w2.w;
        e1 += r.x * w3.x + r.y * w3.y + r.z * w3.z + r.w * w3.w;
    }
#pragma unroll
    for (int off = 16; off > 0; off >>= 1) {
        s0 += __shfl_down_sync(0xFFFFFFFFu, s0, off);
        s1 += __shfl_down_sync(0xFFFFFFFFu, s1, off);
        e0 += __shfl_down_sync(0xFFFFFFFFu, e0, off);
        e1 += __shfl_down_sync(0xFFFFFFFFu, e1, off);
    }
    if (lane == 0) {
        s0 += bs[0]; s1 += bs[1];
        e0 += be[0]; e1 += be[1];
        const bool m  = (mask[t] != 0);
        const bool sc = m && (s0 <= s1);
        const bool ec = m && (e0 <= e1);
        const float score_s = s0 * Wm[0] + s1 * Wm[1];
        const float score_e = e0 * Wm[2] + e1 * Wm[3];
        g_sS[t] = sc ? score_s : -1e30f;
        g_sE[t] = ec ? score_e : -1e30f;
    }
}

// ---------------------------------------------------------------------------
// Phase 2 (per batch): fill the (S,S) pair grid for one batch. Pure
// store-bandwidth kernel (measured-best R1 form: 4 el/thread, plain stores).
// ---------------------------------------------------------------------------
__global__ __launch_bounds__(256) void pair_kernel(
    float* __restrict__ out_valid,   // already offset to this batch
    float* __restrict__ out_score,   // already offset to this batch
    const float* __restrict__ bm,
    int tok_base)                    // b * SS
{
    const long long tid = (long long)blockIdx.x * blockDim.x + threadIdx.x;
    const int  j   = (int)(tid & (SS / 4 - 1)) * 4;  // 512 threads per row
    const int  i   = (int)(tid >> 9);                // row within batch

    const float sSv = g_sS[tok_base + i];
    const float4 ev = *reinterpret_cast<const float4*>(&g_sE[tok_base + j]);
    const float bmv = bm[0];

    float p0 = sSv + ev.x + bmv;
    float p1 = sSv + ev.y + bmv;
    float p2 = sSv + ev.z + bmv;
    float p3 = sSv + ev.w + bmv;

    const bool v0 = (i <= j + 0) && (p0 > 0.f);
    const bool v1 = (i <= j + 1) && (p1 > 0.f);
    const bool v2 = (i <= j + 2) && (p2 > 0.f);
    const bool v3 = (i <= j + 3) && (p3 > 0.f);

    float4 vo, so;
    vo.x = v0 ? 1.f : 0.f;  so.x = v0 ? p0 : 0.f;
    vo.y = v1 ? 1.f : 0.f;  so.y = v1 ? p1 : 0.f;
    vo.z = v2 ? 1.f : 0.f;  so.z = v2 ? p2 : 0.f;
    vo.w = v3 ? 1.f : 0.f;  so.w = v3 ? p3 : 0.f;

    const long long o = tid * 4;
    *reinterpret_cast<float4*>(out_valid + o) = vo;
    *reinterpret_cast<float4*>(out_score + o) = so;
}

// One-time resources for the forked-stream pipeline (resource init only;
// the launched work is identical on every call).
static cudaStream_t g_side = nullptr;
static cudaEvent_t  g_evT[BB];
static cudaEvent_t  g_evJoin = nullptr;

extern "C" void kernel_launch(void* const* d_in, const int* in_sizes, int n_in,
                              void* d_out, int out_size)
{
    const float* rep  = (const float*)d_in[0];
    const int*   mask = (const int*)  d_in[1];
    const float* Ws   = (const float*)d_in[2];
    const float* bs   = (const float*)d_in[3];
    const float* We   = (const float*)d_in[4];
    const float* be   = (const float*)d_in[5];
    const float* Wm   = (const float*)d_in[6];
    const float* bm   = (const float*)d_in[7];

    float* out_valid = (float*)d_out;
    float* out_score = out_valid + BSS;

    if (g_side == nullptr) {
        cudaStreamCreateWithFlags(&g_side, cudaStreamNonBlocking);
        for (int b = 0; b < BB; ++b)
            cudaEventCreateWithFlags(&g_evT[b], cudaEventDisableTiming);
        cudaEventCreateWithFlags(&g_evJoin, cudaEventDisableTiming);
    }

    const cudaStream_t main_s = cudaStreamPerThread;  // what <<<>>> targets

    // Pipeline over batches: token(b) on main stream, pair(b) on side stream
    // after token(b) completes; token(b+1) overlaps pair(b).
    for (int b = 0; b < BB; ++b) {
        const int tok_base = b * SS;
        token_kernel<<<SS / 8, 256, 0, main_s>>>(rep, mask, Ws, bs, We, be, Wm,
                                                 tok_base);
        cudaEventRecord(g_evT[b], main_s);
        cudaStreamWaitEvent(g_side, g_evT[b], 0);

        const unsigned blocks = (unsigned)(SSQ / 4 / 256);  // 4096
        pair_kernel<<<blocks, 256, 0, g_side>>>(out_valid + (long long)b * SSQ,
                                                out_score + (long long)b * SSQ,
                                                bm, tok_base);
    }

    // Join the fork back into the main stream before capture ends.
    cudaEventRecord(g_evJoin, g_side);
    cudaStreamWaitEvent(main_s, g_evJoin, 0);
}

// round 10
// speedup vs baseline: 1.7500x; 1.7500x over previous
#include <cuda_runtime.h>
#include <cuda_bf16.h>
#include <cstdint>

// Problem constants (fixed by reference setup_inputs)
#define BB 8
#define SS 2048
#define HH 1024
#define NTOK (BB * SS)                 // 16384
#define BSS ((long long)BB * SS * SS)  // 33,554,432

// Scratch: per-token combined scores. Non-candidates encoded as -1e30 so that
// pair_score = sS + sE + bm is guaranteed <= 0 -> invalid -> outputs 0.
__device__ float g_sS[NTOK];
__device__ float g_sE[NTOK];

// ---------------------------------------------------------------------------
// Phase 1: per-token logits + scalar scores. One warp per token, 8 warps
// per block (measured-best R3 form). Weights staged in shared as SoA ->
// conflict-free LDS.128. rep loaded with evict-first (.cs): zero reuse.
// ---------------------------------------------------------------------------
__global__ __launch_bounds__(256) void token_kernel(
    const float* __restrict__ rep,   // (B,S,H)
    const int*   __restrict__ mask,  // (B,S)
    const float* __restrict__ Ws,    // (H,2)
    const float* __restrict__ bs,    // (2,)
    const float* __restrict__ We,    // (H,2)
    const float* __restrict__ be,    // (2,)
    const float* __restrict__ Wm)    // (4,1)
{
    __shared__ float s_w0[HH];  // Ws[:,0]
    __shared__ float s_w1[HH];  // Ws[:,1]
    __shared__ float s_w2[HH];  // We[:,0]
    __shared__ float s_w3[HH];  // We[:,1]
    for (int h = threadIdx.x; h < HH; h += blockDim.x) {
        s_w0[h] = Ws[2 * h];
        s_w1[h] = Ws[2 * h + 1];
        s_w2[h] = We[2 * h];
        s_w3[h] = We[2 * h + 1];
    }
    __syncthreads();

    const int warp = threadIdx.x >> 5;
    const int lane = threadIdx.x & 31;
    const int t = blockIdx.x * 8 + warp;   // 2048 blocks * 8 warps = 16384 tokens

    const float4* __restrict__ r4 =
        reinterpret_cast<const float4*>(rep + (size_t)t * HH);

    float s0 = 0.f, s1 = 0.f, e0 = 0.f, e1 = 0.f;
#pragma unroll
    for (int it = 0; it < HH / 128; ++it) {   // 8 iterations of float4
        const int idx = it * 32 + lane;
        const float4 r  = __ldcs(&r4[idx]);
        const float4 w0 = *reinterpret_cast<const float4*>(&s_w0[idx * 4]);
        const float4 w1 = *reinterpret_cast<const float4*>(&s_w1[idx * 4]);
        const float4 w2 = *reinterpret_cast<const float4*>(&s_w2[idx * 4]);
        const float4 w3 = *reinterpret_cast<const float4*>(&s_w3[idx * 4]);
        s0 += r.x * w0.x + r.y * w0.y + r.z * w0.z + r.w * w0.w;
        s1 += r.x * w1.x + r.y * w1.y + r.z * w1.z + r.w * w1.w;
        e0 += r.x * w2.x + r.y * w2.y + r.z * w2.z + r.w * w2.w;
        e1 += r.x * w3.x + r.y * w3.y + r.z * w3.z + r.w * w3.w;
    }
#pragma unroll
    for (int off = 16; off > 0; off >>= 1) {
        s0 += __shfl_down_sync(0xFFFFFFFFu, s0, off);
        s1 += __shfl_down_sync(0xFFFFFFFFu, s1, off);
        e0 += __shfl_down_sync(0xFFFFFFFFu, e0, off);
        e1 += __shfl_down_sync(0xFFFFFFFFu, e1, off);
    }
    if (lane == 0) {
        s0 += bs[0]; s1 += bs[1];
        e0 += be[0]; e1 += be[1];
        const bool m  = (mask[t] != 0);
        const bool sc = m && (s0 <= s1);
        const bool ec = m && (e0 <= e1);
        const float score_s = s0 * Wm[0] + s1 * Wm[1];
        const float score_e = e0 * Wm[2] + e1 * Wm[3];
        g_sS[t] = sc ? score_s : -1e30f;
        g_sE[t] = ec ? score_e : -1e30f;
    }
}

// ---------------------------------------------------------------------------
// Phase 2: fill the (B,S,S) pair grid. Pure store-bandwidth kernel.
// Monolithic grid, 4 el/thread, plain float4 stores (measured-best R1 form).
// ---------------------------------------------------------------------------
__global__ __launch_bounds__(256) void pair_kernel(
    float* __restrict__ out_valid,
    float* __restrict__ out_score,
    const float* __restrict__ bm)
{
    const long long tid = (long long)blockIdx.x * blockDim.x + threadIdx.x;
    const int  j   = (int)(tid & (SS / 4 - 1)) * 4;  // 512 threads per row
    const long long row = tid >> 9;                  // row = b*S + i
    const int  i   = (int)(row & (SS - 1));

    const float sSv = g_sS[row];
    const long long ebase = row - i;                 // b*S
    const float4 ev = *reinterpret_cast<const float4*>(&g_sE[ebase + j]);
    const float bmv = bm[0];

    float p0 = sSv + ev.x + bmv;
    float p1 = sSv + ev.y + bmv;
    float p2 = sSv + ev.z + bmv;
    float p3 = sSv + ev.w + bmv;

    const bool v0 = (i <= j + 0) && (p0 > 0.f);
    const bool v1 = (i <= j + 1) && (p1 > 0.f);
    const bool v2 = (i <= j + 2) && (p2 > 0.f);
    const bool v3 = (i <= j + 3) && (p3 > 0.f);

    float4 vo, so;
    vo.x = v0 ? 1.f : 0.f;  so.x = v0 ? p0 : 0.f;
    vo.y = v1 ? 1.f : 0.f;  so.y = v1 ? p1 : 0.f;
    vo.z = v2 ? 1.f : 0.f;  so.z = v2 ? p2 : 0.f;
    vo.w = v3 ? 1.f : 0.f;  so.w = v3 ? p3 : 0.f;

    const long long o = tid * 4;
    *reinterpret_cast<float4*>(out_valid + o) = vo;
    *reinterpret_cast<float4*>(out_score + o) = so;
}

extern "C" void kernel_launch(void* const* d_in, const int* in_sizes, int n_in,
                              void* d_out, int out_size)
{
    const float* rep  = (const float*)d_in[0];
    const int*   mask = (const int*)  d_in[1];
    const float* Ws   = (const float*)d_in[2];
    const float* bs   = (const float*)d_in[3];
    const float* We   = (const float*)d_in[4];
    const float* be   = (const float*)d_in[5];
    const float* Wm   = (const float*)d_in[6];
    const float* bm   = (const float*)d_in[7];

    float* out_valid = (float*)d_out;
    float* out_score = out_valid + BSS;

    // Phase 1: 16384 tokens, one warp each, 8 warps per block.
    token_kernel<<<NTOK / 8, 256>>>(rep, mask, Ws, bs, We, be, Wm);

    // Phase 2: BSS/4 threads, monolithic grid.
    const long long nthreads = BSS / 4;
    pair_kernel<<<(unsigned)(nthreads / 256), 256>>>(out_valid, out_score, bm);
}